// round 5
// baseline (speedup 1.0000x reference)
#include <cuda_runtime.h>
#include <cstdint>

// ---------------------------------------------------------------------------
// DummyGCN4: 4-layer GCN, output = h3[node 1] only.
// R5: backward-slice with TMA-fed edge scans. Each scan CTA bulk-copies a
// 4096-edge chunk of dst into SMEM via cp.async.bulk (UBLKCP) + mbarrier,
// then filters from SMEM. This replaces the per-thread LDG path (measured
// flat ~9us/scan) with the TMA engine's deep MLP.
// ---------------------------------------------------------------------------

#define MAXN 50048
#define BMW  1568
#define OUT_NODE 1
#define CHUNK 4096          // edges per CTA
#define STHR  256
#define E1CAP  8192
#define E2CAP  32768
#define EBCAP  262144

__device__ unsigned g_B0[BMW], g_B1[BMW], g_B2[BMW];
__device__ int   g_list1[MAXN], g_list2[MAXN];
__device__ int   g_cnt1, g_cnt2;
__device__ int   g_e1s[E1CAP];                 __device__ int g_e1n;
__device__ int   g_e2s[E2CAP],  g_e2d[E2CAP];  __device__ int g_e2n;
__device__ int   g_ebs[EBCAP],  g_ebd[EBCAP];  __device__ int g_ebn;
__device__ float g_agg0[MAXN];
__device__ float g_agg1[(size_t)MAXN * 64];
__device__ float g_x2[(size_t)MAXN * 64];
__device__ float g_agg2[(size_t)MAXN * 64];
__device__ float g_x3[MAXN];

__device__ __forceinline__ float lrelu(float x) { return x >= 0.f ? x : 0.01f * x; }
__device__ __forceinline__ bool tb(const unsigned* b, int i) {
    return (b[i >> 5] >> (i & 31)) & 1u;
}
__device__ __forceinline__ void zero64(float* a) {
    float4 z = make_float4(0.f, 0.f, 0.f, 0.f);
    float4* a4 = (float4*)a;
    #pragma unroll
    for (int j = 0; j < 16; j++) a4[j] = z;
}
__device__ __forceinline__ unsigned smem_u32(const void* p) {
    unsigned a;
    asm("{ .reg .u64 t; cvta.to.shared.u64 t, %1; cvt.u32.u64 %0, t; }"
        : "=r"(a) : "l"(p));
    return a;
}
__device__ __forceinline__ void mbar_init(unsigned addr) {
    asm volatile("mbarrier.init.shared.b64 [%0], %1;" :: "r"(addr), "r"(1) : "memory");
}
__device__ __forceinline__ void mbar_expect(unsigned addr, unsigned bytes) {
    asm volatile("mbarrier.arrive.expect_tx.shared.b64 _, [%0], %1;"
                 :: "r"(addr), "r"(bytes) : "memory");
}
__device__ __forceinline__ void bulk_g2s(unsigned smem_dst, const void* gsrc,
                                         unsigned bytes, unsigned mbar) {
    asm volatile("cp.async.bulk.shared::cluster.global.mbarrier::complete_tx::bytes "
                 "[%0], [%1], %2, [%3];"
                 :: "r"(smem_dst), "l"(gsrc), "r"(bytes), "r"(mbar) : "memory");
}
__device__ __forceinline__ void mbar_wait0(unsigned addr) {
    unsigned done = 0;
    while (!done) {
        asm volatile(
            "{\n\t.reg .pred p;\n\t"
            "mbarrier.try_wait.parity.acquire.cta.shared::cta.b64 p, [%1], 0, 0x989680;\n\t"
            "selp.b32 %0, 1, 0, p;\n\t}"
            : "=r"(done) : "r"(addr) : "memory");
    }
}

// Load this CTA's dst chunk into s_dst via TMA bulk copy. Returns edge count.
__device__ __forceinline__ int load_chunk(const int* __restrict__ g, int E,
                                          int* s_dst, unsigned long long* mbar) {
    int base = blockIdx.x * CHUNK;
    int cnt = min(CHUNK, E - base);
    unsigned mb = smem_u32(mbar);
    if (threadIdx.x == 0) mbar_init(mb);
    __syncthreads();
    int vec_bytes = (cnt * 4) & ~15;            // bulk copy needs 16B multiple
    if (threadIdx.x == 0 && vec_bytes > 0) {
        mbar_expect(mb, (unsigned)vec_bytes);
        bulk_g2s(smem_u32(s_dst), g + base, (unsigned)vec_bytes, mb);
    }
    // scalar tail (at most 3 edges)
    for (int i = (vec_bytes >> 2) + threadIdx.x; i < cnt; i += blockDim.x)
        s_dst[i] = g[base + i];
    if (vec_bytes > 0) mbar_wait0(mb);
    __syncthreads();
    return cnt;
}

// ---------------- clear ----------------
__global__ void k_clear() {
    int t = blockIdx.x * blockDim.x + threadIdx.x;
    if (t < BMW) { g_B0[t] = 0; g_B1[t] = 0; g_B2[t] = 0; }
    if (t == 0) { g_cnt1 = 0; g_cnt2 = 0; g_e1n = 0; g_e2n = 0; g_ebn = 0; }
}

// ---------------- scan1: dst == OUT_NODE -> B2/list2/e1 ----------------
__device__ __forceinline__ void hit32(int s) {
    int p = atomicAdd(&g_e1n, 1);
    if (p < E1CAP) g_e1s[p] = s;
    unsigned m = 1u << (s & 31);
    unsigned old = atomicOr(&g_B2[s >> 5], m);
    if (!(old & m)) {
        int q = atomicAdd(&g_cnt2, 1);
        g_list2[q] = s;
        zero64(&g_agg2[(size_t)s * 64]);
    }
}
__global__ void __launch_bounds__(STHR)
k_scan1(const int* __restrict__ src, const int* __restrict__ dst, int E) {
    __shared__ int s_dst[CHUNK];
    __shared__ alignas(8) unsigned long long mbar;
    int cnt = load_chunk(dst, E, s_dst, &mbar);
    int base = blockIdx.x * CHUNK;
    const int4* s4 = (const int4*)s_dst;
    int nv = cnt >> 2;
    for (int i = threadIdx.x; i < nv; i += STHR) {
        int4 d = s4[i];
        int e = base + (i << 2);
        if (d.x == OUT_NODE) hit32(__ldg(&src[e + 0]));
        if (d.y == OUT_NODE) hit32(__ldg(&src[e + 1]));
        if (d.z == OUT_NODE) hit32(__ldg(&src[e + 2]));
        if (d.w == OUT_NODE) hit32(__ldg(&src[e + 3]));
    }
    for (int i = (nv << 2) + threadIdx.x; i < cnt; i += STHR)
        if (s_dst[i] == OUT_NODE) hit32(__ldg(&src[base + i]));
}

// ---------------- scan2: dst in B2 -> B1/list1/e2 ----------------
__device__ __forceinline__ void hit21(int s, int d) {
    int p = atomicAdd(&g_e2n, 1);
    if (p < E2CAP) { g_e2s[p] = s; g_e2d[p] = d; }
    unsigned m = 1u << (s & 31);
    unsigned old = atomicOr(&g_B1[s >> 5], m);
    if (!(old & m)) {
        int q = atomicAdd(&g_cnt1, 1);
        g_list1[q] = s;
        zero64(&g_agg1[(size_t)s * 64]);
    }
}
__global__ void __launch_bounds__(STHR)
k_scan2(const int* __restrict__ src, const int* __restrict__ dst, int E) {
    __shared__ int s_dst[CHUNK];
    __shared__ alignas(8) unsigned long long mbar;
    int cnt = load_chunk(dst, E, s_dst, &mbar);
    int base = blockIdx.x * CHUNK;
    const int4* s4 = (const int4*)s_dst;
    int nv = cnt >> 2;
    for (int i = threadIdx.x; i < nv; i += STHR) {
        int4 d = s4[i];
        int e = base + (i << 2);
        if (tb(g_B2, d.x)) hit21(__ldg(&src[e + 0]), d.x);
        if (tb(g_B2, d.y)) hit21(__ldg(&src[e + 1]), d.y);
        if (tb(g_B2, d.z)) hit21(__ldg(&src[e + 2]), d.z);
        if (tb(g_B2, d.w)) hit21(__ldg(&src[e + 3]), d.w);
    }
    for (int i = (nv << 2) + threadIdx.x; i < cnt; i += STHR) {
        int d = s_dst[i];
        if (tb(g_B2, d)) hit21(__ldg(&src[base + i]), d);
    }
}

// ---------------- scan3: dst in B1 -> B0 + eb capture ----------------
__device__ __forceinline__ void hit10(int s, int d) {
    int p = atomicAdd(&g_ebn, 1);
    if (p < EBCAP) { g_ebs[p] = s; g_ebd[p] = d; }
    unsigned m = 1u << (s & 31);
    unsigned old = atomicOr(&g_B0[s >> 5], m);
    if (!(old & m)) g_agg0[s] = 0.f;
}
__global__ void __launch_bounds__(STHR)
k_scan3(const int* __restrict__ src, const int* __restrict__ dst, int E) {
    __shared__ int s_dst[CHUNK];
    __shared__ alignas(8) unsigned long long mbar;
    int cnt = load_chunk(dst, E, s_dst, &mbar);
    int base = blockIdx.x * CHUNK;
    const int4* s4 = (const int4*)s_dst;
    int nv = cnt >> 2;
    for (int i = threadIdx.x; i < nv; i += STHR) {
        int4 d = s4[i];
        int e = base + (i << 2);
        if (tb(g_B1, d.x)) hit10(__ldg(&src[e + 0]), d.x);
        if (tb(g_B1, d.y)) hit10(__ldg(&src[e + 1]), d.y);
        if (tb(g_B1, d.z)) hit10(__ldg(&src[e + 2]), d.z);
        if (tb(g_B1, d.w)) hit10(__ldg(&src[e + 3]), d.w);
    }
    for (int i = (nv << 2) + threadIdx.x; i < cnt; i += STHR) {
        int d = s_dst[i];
        if (tb(g_B1, d)) hit10(__ldg(&src[base + i]), d);
    }
}

// ---------------- scan4: dst in B0 -> agg0[d] += in_feat[src] ----------------
__global__ void __launch_bounds__(STHR)
k_scan4(const int* __restrict__ src, const int* __restrict__ dst,
        const float* __restrict__ in_feat, int E) {
    __shared__ int s_dst[CHUNK];
    __shared__ alignas(8) unsigned long long mbar;
    int cnt = load_chunk(dst, E, s_dst, &mbar);
    int base = blockIdx.x * CHUNK;
    const int4* s4 = (const int4*)s_dst;
    int nv = cnt >> 2;
    for (int i = threadIdx.x; i < nv; i += STHR) {
        int4 d = s4[i];
        int e = base + (i << 2);
        if (tb(g_B0, d.x)) atomicAdd(&g_agg0[d.x], __ldg(&in_feat[__ldg(&src[e + 0])]));
        if (tb(g_B0, d.y)) atomicAdd(&g_agg0[d.y], __ldg(&in_feat[__ldg(&src[e + 1])]));
        if (tb(g_B0, d.z)) atomicAdd(&g_agg0[d.z], __ldg(&in_feat[__ldg(&src[e + 2])]));
        if (tb(g_B0, d.w)) atomicAdd(&g_agg0[d.w], __ldg(&in_feat[__ldg(&src[e + 3])]));
    }
    for (int i = (nv << 2) + threadIdx.x; i < cnt; i += STHR) {
        int d = s_dst[i];
        if (tb(g_B0, d)) atomicAdd(&g_agg0[d], __ldg(&in_feat[__ldg(&src[base + i])]));
    }
}

// ---------------- agg1: agg1[d][:] += lrelu(agg0[s]*W0+b0), warp/edge -------
__global__ void k_agg1(const float* __restrict__ W0, const float* __restrict__ b0) {
    int n = min(g_ebn, EBCAP);
    int lane = threadIdx.x & 31;
    int warp = (blockIdx.x * blockDim.x + threadIdx.x) >> 5;
    int nw = (gridDim.x * blockDim.x) >> 5;
    float w0a = __ldg(&W0[lane]), w0b = __ldg(&W0[lane + 32]);
    float b0a = __ldg(&b0[lane]), b0b = __ldg(&b0[lane + 32]);
    for (int i = warp; i < n; i += nw) {
        int s = g_ebs[i], d = g_ebd[i];
        float a0 = g_agg0[s];
        float* a = &g_agg1[(size_t)d * 64];
        atomicAdd(&a[lane],      lrelu(fmaf(a0, w0a, b0a)));
        atomicAdd(&a[lane + 32], lrelu(fmaf(a0, w0b, b0b)));
    }
}

// ---------------- h1x2: per node in list1 (warp/node) ----------------
__global__ void k_h1x2(const float* __restrict__ W1, const float* __restrict__ b1,
                       const float* __restrict__ W2) {
    int n = g_cnt1;
    int lane = threadIdx.x & 31;
    int warp = (blockIdx.x * blockDim.x + threadIdx.x) >> 5;
    int nw = (gridDim.x * blockDim.x) >> 5;
    for (int i = warp; i < n; i += nw) {
        int v = g_list1[i];
        float a0 = g_agg1[(size_t)v * 64 + lane];
        float a1 = g_agg1[(size_t)v * 64 + lane + 32];
        float h0r = __ldg(&b1[lane]);
        float h1r = __ldg(&b1[lane + 32]);
        float h2r = __ldg(&b1[lane + 64]);
        float h3r = __ldg(&b1[lane + 96]);
        #pragma unroll
        for (int k = 0; k < 64; k++) {
            float ak = __shfl_sync(0xffffffffu, (k < 32) ? a0 : a1, k & 31);
            const float* wr = &W1[k * 128];
            h0r = fmaf(ak, __ldg(&wr[lane]),      h0r);
            h1r = fmaf(ak, __ldg(&wr[lane + 32]), h1r);
            h2r = fmaf(ak, __ldg(&wr[lane + 64]), h2r);
            h3r = fmaf(ak, __ldg(&wr[lane + 96]), h3r);
        }
        float h[4] = { lrelu(h0r), lrelu(h1r), lrelu(h2r), lrelu(h3r) };
        float x0 = 0.f, x1 = 0.f;
        #pragma unroll
        for (int k = 0; k < 128; k++) {
            float hk = __shfl_sync(0xffffffffu, h[k >> 5], k & 31);
            const float* wr = &W2[k * 64];
            x0 = fmaf(hk, __ldg(&wr[lane]),      x0);
            x1 = fmaf(hk, __ldg(&wr[lane + 32]), x1);
        }
        g_x2[(size_t)v * 64 + lane]      = x0;
        g_x2[(size_t)v * 64 + lane + 32] = x1;
    }
}

// ---------------- tail: agg2 + h2x3 + final reduce + out (1 block) ----------
__global__ void __launch_bounds__(1024, 1)
k_tail(const float* __restrict__ b2, const float* __restrict__ W3,
       const float* __restrict__ b3, float* __restrict__ out) {
    int lane = threadIdx.x & 31;
    int bw = threadIdx.x >> 5;

    int n2 = min(g_e2n, E2CAP);
    for (int i = bw; i < n2; i += 32) {
        int s = g_e2s[i], d = g_e2d[i];
        float* a = &g_agg2[(size_t)d * 64];
        atomicAdd(&a[lane],      __ldcg(&g_x2[(size_t)s * 64 + lane]));
        atomicAdd(&a[lane + 32], __ldcg(&g_x2[(size_t)s * 64 + lane + 32]));
    }
    __syncthreads();

    int n3 = g_cnt2;
    for (int i = bw; i < n3; i += 32) {
        int v = g_list2[i];
        float ya = lrelu(__ldcg(&g_agg2[(size_t)v * 64 + lane])      + __ldg(&b2[lane]));
        float yb = lrelu(__ldcg(&g_agg2[(size_t)v * 64 + lane + 32]) + __ldg(&b2[lane + 32]));
        float p = fmaf(ya, __ldg(&W3[lane]), yb * __ldg(&W3[lane + 32]));
        #pragma unroll
        for (int o = 16; o; o >>= 1) p += __shfl_down_sync(0xffffffffu, p, o);
        if (lane == 0) g_x3[v] = p;
    }
    __syncthreads();

    __shared__ float red[32];
    int n1 = min(g_e1n, E1CAP);
    float s = 0.f;
    for (int i = threadIdx.x; i < n1; i += 1024) s += __ldcg(&g_x3[g_e1s[i]]);
    #pragma unroll
    for (int o = 16; o; o >>= 1) s += __shfl_down_sync(0xffffffffu, s, o);
    if (lane == 0) red[bw] = s;
    __syncthreads();
    if (threadIdx.x < 32) {
        float t = red[lane];
        #pragma unroll
        for (int o = 16; o; o >>= 1) t += __shfl_down_sync(0xffffffffu, t, o);
        if (lane == 0) out[0] = lrelu(t + __ldg(&b3[0]));
    }
}

// ---------------------------------------------------------------------------
extern "C" void kernel_launch(void* const* d_in, const int* in_sizes, int n_in,
                              void* d_out, int out_size) {
    const float* in_feat = (const float*)d_in[0];
    const int*   src     = (const int*)  d_in[1];
    const int*   dst     = (const int*)  d_in[2];
    const float* W0 = (const float*)d_in[3];
    const float* b0 = (const float*)d_in[4];
    const float* W1 = (const float*)d_in[5];
    const float* b1 = (const float*)d_in[6];
    const float* W2 = (const float*)d_in[7];
    const float* b2 = (const float*)d_in[8];
    const float* W3 = (const float*)d_in[9];
    const float* b3 = (const float*)d_in[10];
    float* out = (float*)d_out;

    int E = in_sizes[1];
    int cb = (E + CHUNK - 1) / CHUNK;        // ~196 CTAs for 800k edges

    k_clear<<<(BMW + 255) / 256, 256>>>();
    k_scan1<<<cb, STHR>>>(src, dst, E);
    k_scan2<<<cb, STHR>>>(src, dst, E);
    k_scan3<<<cb, STHR>>>(src, dst, E);
    k_scan4<<<cb, STHR>>>(src, dst, in_feat, E);
    k_agg1<<<256, 256>>>(W0, b0);
    k_h1x2<<<128, 256>>>(W1, b1, W2);
    k_tail<<<1, 1024>>>(b2, W3, b3, out);
}

// round 6
// speedup vs baseline: 1.0853x; 1.0853x over previous
#include <cuda_runtime.h>

// ---------------------------------------------------------------------------
// DummyGCN4: 4-layer GCN, output = h3[node 1] only.
// R6: R2's proven backward-slice scans, with graph-node count cut 12 -> 7:
//   scan32: capture node-1 in-edges -> B2/list2/e1 (zero agg2 on insert)
//   scan21: dst in B2 -> B1/list1/e2 (zero agg1 on insert)
//   scan10: dst in B1 -> B0 + eb capture (zero agg0 on insert)
//   agg0:   dst in B0 -> agg0[d] += in_feat[src]
//   agg1:   agg1[d][:] += lrelu(agg0[s]*W0+b0) over eb (h0 fused)
//   h1x2:   per node in list1: h1 = lrelu(agg1@W1+b1); x2 = h1@W2
//   tail:   agg2 over e2, h2/x3, final reduce, out — then SELF-CLEANUP so the
//           next call starts from zeroed state (no clear kernel needed; static
//           __device__ arrays are zero-initialized for the very first call).
// ---------------------------------------------------------------------------

#define MAXN 50048
#define BMW  1568
#define OUT_NODE 1
#define E1CAP  8192       // edges with dst == OUT_NODE   (expect ~16)
#define E2CAP  32768      // edges with dst in B2         (expect ~256)
#define EBCAP  262144     // edges with dst in B1         (expect ~4k)

__device__ unsigned g_B0[BMW], g_B1[BMW], g_B2[BMW];
__device__ int   g_list1[MAXN], g_list2[MAXN];
__device__ int   g_cnt1, g_cnt2;
__device__ int   g_e1s[E1CAP];                 __device__ int g_e1n;
__device__ int   g_e2s[E2CAP],  g_e2d[E2CAP];  __device__ int g_e2n;
__device__ int   g_ebs[EBCAP],  g_ebd[EBCAP];  __device__ int g_ebn;
__device__ float g_agg0[MAXN];
__device__ float g_agg1[(size_t)MAXN * 64];
__device__ float g_x2[(size_t)MAXN * 64];
__device__ float g_agg2[(size_t)MAXN * 64];
__device__ float g_x3[MAXN];

__device__ __forceinline__ float lrelu(float x) { return x >= 0.f ? x : 0.01f * x; }
__device__ __forceinline__ bool tb(const unsigned* b, int i) {
    return (b[i >> 5] >> (i & 31)) & 1u;
}
__device__ __forceinline__ void zero64(float* a) {
    float4 z = make_float4(0.f, 0.f, 0.f, 0.f);
    float4* a4 = (float4*)a;
    #pragma unroll
    for (int j = 0; j < 16; j++) a4[j] = z;
}

// ---------------- scan32: dst == OUT_NODE ----------------
__device__ __forceinline__ void hit32(const int* __restrict__ src, int e) {
    int s = __ldg(&src[e]);
    int p = atomicAdd(&g_e1n, 1);
    if (p < E1CAP) g_e1s[p] = s;
    unsigned m = 1u << (s & 31);
    unsigned old = atomicOr(&g_B2[s >> 5], m);
    if (!(old & m)) {
        int q = atomicAdd(&g_cnt2, 1);
        g_list2[q] = s;
        zero64(&g_agg2[(size_t)s * 64]);
    }
}
__global__ void k_scan32(const int* __restrict__ src, const int* __restrict__ dst, int E) {
    int t = blockIdx.x * blockDim.x + threadIdx.x;
    int base = t * 4;
    if (base + 3 < E) {
        int4 d4 = __ldg((const int4*)(dst + base));
        if (d4.x == OUT_NODE) hit32(src, base + 0);
        if (d4.y == OUT_NODE) hit32(src, base + 1);
        if (d4.z == OUT_NODE) hit32(src, base + 2);
        if (d4.w == OUT_NODE) hit32(src, base + 3);
    } else {
        for (int e = base; e < E; e++) if (__ldg(&dst[e]) == OUT_NODE) hit32(src, e);
    }
}

// ---------------- scan21: dst in B2 ----------------
__device__ __forceinline__ void hit21(const int* __restrict__ src, int e, int d) {
    int s = __ldg(&src[e]);
    int p = atomicAdd(&g_e2n, 1);
    if (p < E2CAP) { g_e2s[p] = s; g_e2d[p] = d; }
    unsigned m = 1u << (s & 31);
    unsigned old = atomicOr(&g_B1[s >> 5], m);
    if (!(old & m)) {
        int q = atomicAdd(&g_cnt1, 1);
        g_list1[q] = s;
        zero64(&g_agg1[(size_t)s * 64]);
    }
}
__global__ void k_scan21(const int* __restrict__ src, const int* __restrict__ dst, int E) {
    int t = blockIdx.x * blockDim.x + threadIdx.x;
    int base = t * 4;
    if (base + 3 < E) {
        int4 d4 = __ldg((const int4*)(dst + base));
        if (tb(g_B2, d4.x)) hit21(src, base + 0, d4.x);
        if (tb(g_B2, d4.y)) hit21(src, base + 1, d4.y);
        if (tb(g_B2, d4.z)) hit21(src, base + 2, d4.z);
        if (tb(g_B2, d4.w)) hit21(src, base + 3, d4.w);
    } else {
        for (int e = base; e < E; e++) { int d = __ldg(&dst[e]); if (tb(g_B2, d)) hit21(src, e, d); }
    }
}

// ---------------- scan10: dst in B1 -> B0 + eb ----------------
__device__ __forceinline__ void hit10(const int* __restrict__ src, int e, int d) {
    int s = __ldg(&src[e]);
    int p = atomicAdd(&g_ebn, 1);
    if (p < EBCAP) { g_ebs[p] = s; g_ebd[p] = d; }
    unsigned m = 1u << (s & 31);
    unsigned old = atomicOr(&g_B0[s >> 5], m);
    if (!(old & m)) g_agg0[s] = 0.f;
}
__global__ void k_scan10(const int* __restrict__ src, const int* __restrict__ dst, int E) {
    int t = blockIdx.x * blockDim.x + threadIdx.x;
    int base = t * 4;
    if (base + 3 < E) {
        int4 d4 = __ldg((const int4*)(dst + base));
        if (tb(g_B1, d4.x)) hit10(src, base + 0, d4.x);
        if (tb(g_B1, d4.y)) hit10(src, base + 1, d4.y);
        if (tb(g_B1, d4.z)) hit10(src, base + 2, d4.z);
        if (tb(g_B1, d4.w)) hit10(src, base + 3, d4.w);
    } else {
        for (int e = base; e < E; e++) { int d = __ldg(&dst[e]); if (tb(g_B1, d)) hit10(src, e, d); }
    }
}

// ---------------- agg0: dst in B0 ----------------
__global__ void k_agg0(const int* __restrict__ src, const int* __restrict__ dst, int E,
                       const float* __restrict__ in_feat) {
    int t = blockIdx.x * blockDim.x + threadIdx.x;
    int base = t * 4;
    if (base + 3 < E) {
        int4 d4 = __ldg((const int4*)(dst + base));
        if (tb(g_B0, d4.x)) atomicAdd(&g_agg0[d4.x], __ldg(&in_feat[__ldg(&src[base + 0])]));
        if (tb(g_B0, d4.y)) atomicAdd(&g_agg0[d4.y], __ldg(&in_feat[__ldg(&src[base + 1])]));
        if (tb(g_B0, d4.z)) atomicAdd(&g_agg0[d4.z], __ldg(&in_feat[__ldg(&src[base + 2])]));
        if (tb(g_B0, d4.w)) atomicAdd(&g_agg0[d4.w], __ldg(&in_feat[__ldg(&src[base + 3])]));
    } else {
        for (int e = base; e < E; e++) {
            int d = __ldg(&dst[e]);
            if (tb(g_B0, d)) atomicAdd(&g_agg0[d], __ldg(&in_feat[__ldg(&src[e])]));
        }
    }
}

// ---------------- agg1: agg1[d][:] += lrelu(agg0[s]*W0+b0), warp/edge -------
__global__ void k_agg1(const float* __restrict__ W0, const float* __restrict__ b0) {
    int n = min(g_ebn, EBCAP);
    int lane = threadIdx.x & 31;
    int warp = (blockIdx.x * blockDim.x + threadIdx.x) >> 5;
    int nw = (gridDim.x * blockDim.x) >> 5;
    float w0a = __ldg(&W0[lane]), w0b = __ldg(&W0[lane + 32]);
    float b0a = __ldg(&b0[lane]), b0b = __ldg(&b0[lane + 32]);
    for (int i = warp; i < n; i += nw) {
        int s = g_ebs[i], d = g_ebd[i];
        float a0 = g_agg0[s];
        float* a = &g_agg1[(size_t)d * 64];
        atomicAdd(&a[lane],      lrelu(fmaf(a0, w0a, b0a)));
        atomicAdd(&a[lane + 32], lrelu(fmaf(a0, w0b, b0b)));
    }
}

// ---------------- h1x2: per node in list1 (warp/node) ----------------
__global__ void k_h1x2(const float* __restrict__ W1, const float* __restrict__ b1,
                       const float* __restrict__ W2) {
    int n = g_cnt1;
    int lane = threadIdx.x & 31;
    int warp = (blockIdx.x * blockDim.x + threadIdx.x) >> 5;
    int nw = (gridDim.x * blockDim.x) >> 5;
    for (int i = warp; i < n; i += nw) {
        int v = g_list1[i];
        float a0 = g_agg1[(size_t)v * 64 + lane];
        float a1 = g_agg1[(size_t)v * 64 + lane + 32];
        float h0r = __ldg(&b1[lane]);
        float h1r = __ldg(&b1[lane + 32]);
        float h2r = __ldg(&b1[lane + 64]);
        float h3r = __ldg(&b1[lane + 96]);
        #pragma unroll
        for (int k = 0; k < 64; k++) {
            float ak = __shfl_sync(0xffffffffu, (k < 32) ? a0 : a1, k & 31);
            const float* wr = &W1[k * 128];
            h0r = fmaf(ak, __ldg(&wr[lane]),      h0r);
            h1r = fmaf(ak, __ldg(&wr[lane + 32]), h1r);
            h2r = fmaf(ak, __ldg(&wr[lane + 64]), h2r);
            h3r = fmaf(ak, __ldg(&wr[lane + 96]), h3r);
        }
        float h[4] = { lrelu(h0r), lrelu(h1r), lrelu(h2r), lrelu(h3r) };
        float x0 = 0.f, x1 = 0.f;
        #pragma unroll
        for (int k = 0; k < 128; k++) {
            float hk = __shfl_sync(0xffffffffu, h[k >> 5], k & 31);
            const float* wr = &W2[k * 64];
            x0 = fmaf(hk, __ldg(&wr[lane]),      x0);
            x1 = fmaf(hk, __ldg(&wr[lane + 32]), x1);
        }
        g_x2[(size_t)v * 64 + lane]      = x0;
        g_x2[(size_t)v * 64 + lane + 32] = x1;
    }
}

// ---------------- tail: agg2 + h2x3 + final + out + CLEANUP (1 block) -------
__global__ void __launch_bounds__(1024, 1)
k_tail(const float* __restrict__ b2, const float* __restrict__ W3,
       const float* __restrict__ b3, float* __restrict__ out) {
    int lane = threadIdx.x & 31;
    int bw = threadIdx.x >> 5;

    // agg2[d][:] += x2[s][:] over e2 (warp per edge)
    int n2 = min(g_e2n, E2CAP);
    for (int i = bw; i < n2; i += 32) {
        int s = g_e2s[i], d = g_e2d[i];
        float* a = &g_agg2[(size_t)d * 64];
        atomicAdd(&a[lane],      __ldcg(&g_x2[(size_t)s * 64 + lane]));
        atomicAdd(&a[lane + 32], __ldcg(&g_x2[(size_t)s * 64 + lane + 32]));
    }
    __syncthreads();

    // h2 = lrelu(agg2 + b2); x3 = h2 . W3 (warp per node)
    int n3 = g_cnt2;
    for (int i = bw; i < n3; i += 32) {
        int v = g_list2[i];
        float ya = lrelu(__ldcg(&g_agg2[(size_t)v * 64 + lane])      + __ldg(&b2[lane]));
        float yb = lrelu(__ldcg(&g_agg2[(size_t)v * 64 + lane + 32]) + __ldg(&b2[lane + 32]));
        float p = fmaf(ya, __ldg(&W3[lane]), yb * __ldg(&W3[lane + 32]));
        #pragma unroll
        for (int o = 16; o; o >>= 1) p += __shfl_down_sync(0xffffffffu, p, o);
        if (lane == 0) g_x3[v] = p;
    }
    __syncthreads();

    // final: sum x3[src] over node-1 in-edges
    __shared__ float red[32];
    int n1 = min(g_e1n, E1CAP);
    float s = 0.f;
    for (int i = threadIdx.x; i < n1; i += 1024) s += __ldcg(&g_x3[g_e1s[i]]);
    #pragma unroll
    for (int o = 16; o; o >>= 1) s += __shfl_down_sync(0xffffffffu, s, o);
    if (lane == 0) red[bw] = s;
    __syncthreads();
    if (threadIdx.x < 32) {
        float t = red[lane];
        #pragma unroll
        for (int o = 16; o; o >>= 1) t += __shfl_down_sync(0xffffffffu, t, o);
        if (lane == 0) out[0] = lrelu(t + __ldg(&b3[0]));
    }
    __syncthreads();

    // ---- SELF-CLEANUP: restore zeroed state for the next call ----
    // Only bits of captured nodes are set in each bitmap, so zeroing the
    // containing words (plain stores, duplicates fine) restores all-zero.
    int c2 = g_cnt2, c1 = g_cnt1, ne = min(g_ebn, EBCAP);
    for (int i = threadIdx.x; i < c2; i += 1024) { int v = g_list2[i]; g_B2[v >> 5] = 0u; }
    for (int i = threadIdx.x; i < c1; i += 1024) { int v = g_list1[i]; g_B1[v >> 5] = 0u; }
    for (int i = threadIdx.x; i < ne; i += 1024) { int v = g_ebs[i];   g_B0[v >> 5] = 0u; }
    __syncthreads();
    if (threadIdx.x == 0) {
        g_cnt1 = 0; g_cnt2 = 0; g_e1n = 0; g_e2n = 0; g_ebn = 0;
        __threadfence();
    }
}

// ---------------------------------------------------------------------------
extern "C" void kernel_launch(void* const* d_in, const int* in_sizes, int n_in,
                              void* d_out, int out_size) {
    const float* in_feat = (const float*)d_in[0];
    const int*   src     = (const int*)  d_in[1];
    const int*   dst     = (const int*)  d_in[2];
    const float* W0 = (const float*)d_in[3];
    const float* b0 = (const float*)d_in[4];
    const float* W1 = (const float*)d_in[5];
    const float* b1 = (const float*)d_in[6];
    const float* W2 = (const float*)d_in[7];
    const float* b2 = (const float*)d_in[8];
    const float* W3 = (const float*)d_in[9];
    const float* b3 = (const float*)d_in[10];
    float* out = (float*)d_out;

    int E = in_sizes[1];
    int T = (E + 3) / 4;                 // one thread per 4 edges
    int sb = (T + 255) / 256;

    k_scan32<<<sb, 256>>>(src, dst, E);
    k_scan21<<<sb, 256>>>(src, dst, E);
    k_scan10<<<sb, 256>>>(src, dst, E);
    k_agg0<<<sb, 256>>>(src, dst, E, in_feat);
    k_agg1<<<256, 256>>>(W0, b0);
    k_h1x2<<<128, 256>>>(W1, b1, W2);
    k_tail<<<1, 1024>>>(b2, W3, b3, out);
}